// round 4
// baseline (speedup 1.0000x reference)
#include <cuda_runtime.h>

// Problem constants
constexpr int Bn   = 128;
constexpr int Ln   = 336;
constexpr int Nn   = 321;
constexpr int En   = 128;
constexpr int LATn = 64;

constexpr int HN    = Bn * Nn * En;    // 5,259,264
constexpr int LATSZ = Bn * Nn * LATn;  // 2,629,632

// Scratch: x transposed to [B, N, L] (55 MB, static device global — allowed)
__device__ static float g_xp[(size_t)Bn * Nn * Ln];

// ---------------------------------------------------------------------------
// f32x2 packed-math helpers (Blackwell FFMA2 path)
// ---------------------------------------------------------------------------
__device__ __forceinline__ unsigned long long ffma2(unsigned long long a,
                                                    unsigned long long b,
                                                    unsigned long long c) {
    unsigned long long d;
    asm("fma.rn.f32x2 %0, %1, %2, %3;" : "=l"(d) : "l"(a), "l"(b), "l"(c));
    return d;
}
__device__ __forceinline__ unsigned long long bcast2(float w) {
    unsigned long long d;
    asm("mov.b64 %0, {%1, %1};" : "=l"(d) : "f"(w));
    return d;
}
__device__ __forceinline__ float2 unpk(unsigned long long v) {
    float2 r;
    asm("mov.b64 {%0, %1}, %2;" : "=f"(r.x), "=f"(r.y) : "l"(v));
    return r;
}

// ---------------------------------------------------------------------------
// Kernel 1: transpose x [B, L, N] -> g_xp [B, N, L]
// ---------------------------------------------------------------------------
__global__ void transpose_kernel(const float* __restrict__ x) {
    __shared__ float tile[32][33];
    const int b  = blockIdx.z;
    const int n0 = blockIdx.x * 32;
    const int l0 = blockIdx.y * 32;

#pragma unroll
    for (int i = 0; i < 4; i++) {
        int l  = l0 + threadIdx.y + i * 8;
        int nn = n0 + threadIdx.x;
        if (l < Ln && nn < Nn)
            tile[threadIdx.y + i * 8][threadIdx.x] = x[((size_t)b * Ln + l) * Nn + nn];
    }
    __syncthreads();
#pragma unroll
    for (int i = 0; i < 4; i++) {
        int nn = n0 + threadIdx.y + i * 8;
        int l  = l0 + threadIdx.x;
        if (nn < Nn && l < Ln)
            g_xp[((size_t)b * Nn + nn) * Ln + l] = tile[threadIdx.x][threadIdx.y + i * 8];
    }
}

// ---------------------------------------------------------------------------
// Kernel 2: grouped GEMM h[b,n,e] = sum_l xp[b,n,l] * W_embed[n,l,e] + b_embed
//           + fused h_hat = sigmoid(time_x) * h
// grid (Nn, Bn/64), 256 threads. Thread tile: 8 rows (4 f32x2 pairs) x 4 cols.
// ---------------------------------------------------------------------------
constexpr int BM2 = 64;   // batch rows per block
constexpr int LK  = 48;   // k-tile (336 = 7*48)
constexpr int BMP = 66;   // padded row width for xs (keeps 8B align + few conflicts)

__global__ void __launch_bounds__(256, 2) embed_kernel(
    const float* __restrict__ W_embed, const float* __restrict__ b_embed,
    const float* __restrict__ time_x,
    float* __restrict__ h_out, float* __restrict__ hhat_out)
{
    __shared__ float xs[LK][BMP];   // xs[k][m] : m-pairs adjacent
    __shared__ float ws[LK][En];    // ws[k][e]

    const int n    = blockIdx.x;
    const int b0   = blockIdx.y * BM2;
    const int t    = threadIdx.x;
    const int lane = t & 31;
    const int wid  = t >> 5;
    const int m_base = wid * 8;

    unsigned long long acc[4][4];
#pragma unroll
    for (int p = 0; p < 4; p++)
#pragma unroll
        for (int j = 0; j < 4; j++) acc[p][j] = 0ULL;

    for (int kt = 0; kt < Ln; kt += LK) {
        // fill xs: 64 x 48 (coalesced reads along L)
#pragma unroll
        for (int i = 0; i < (BM2 * LK) / 256; i++) {
            int idx = t + i * 256;
            int m = idx / LK;
            int kk = idx - m * LK;
            xs[kk][m] = g_xp[((size_t)(b0 + m) * Nn + n) * Ln + kt + kk];
        }
        // fill ws: 48 x 128 (fully coalesced)
#pragma unroll
        for (int i = 0; i < (LK * En) / 256; i++) {
            int idx = t + i * 256;
            int kk = idx >> 7;
            int e  = idx & 127;
            ws[kk][e] = W_embed[((size_t)n * Ln + kt + kk) * En + e];
        }
        __syncthreads();

#pragma unroll
        for (int kk = 0; kk < LK; kk++) {
            unsigned long long xpair[4];
#pragma unroll
            for (int p = 0; p < 4; p++)
                xpair[p] = *reinterpret_cast<const unsigned long long*>(
                    &xs[kk][m_base + 2 * p]);
#pragma unroll
            for (int j = 0; j < 4; j++) {
                unsigned long long w2 = bcast2(ws[kk][lane + 32 * j]);
#pragma unroll
                for (int p = 0; p < 4; p++)
                    acc[p][j] = ffma2(xpair[p], w2, acc[p][j]);
            }
        }
        __syncthreads();
    }

    // epilogue: bias, write h; sigmoid(time_x)*h -> h_hat
#pragma unroll
    for (int j = 0; j < 4; j++) {
        const int e = lane + 32 * j;
        const float bias = b_embed[n * En + e];
#pragma unroll
        for (int p = 0; p < 4; p++) {
            float2 hv = unpk(acc[p][j]);
            const int b_r = b0 + m_base + 2 * p;
            const int i0 = ((b_r) * Nn + n) * En + e;
            const int i1 = i0 + Nn * En;
            float h0 = hv.x + bias;
            float h1 = hv.y + bias;
            h_out[i0] = h0;
            h_out[i1] = h1;
            float t0 = time_x[i0];
            float t1 = time_x[i1];
            float s0 = 1.0f / (1.0f + __expf(-t0));
            float s1 = 1.0f / (1.0f + __expf(-t1));
            hhat_out[i0] = h0 * s0;
            hhat_out[i1] = h1 * s1;
        }
    }
}

// ---------------------------------------------------------------------------
// Kernel 3: mu/var heads.  out[b,n,0:64]=mu, [64:128]=var (concat W in smem)
// mu[b,n,k] = sum_e hhat[b,n,e] * W_mu[n,e,k] + b_mu[n,k]
// grid (Nn, Bn/64), 256 threads, K=128 in tiles of 32.
// ---------------------------------------------------------------------------
constexpr int KT3 = 32;

__global__ void __launch_bounds__(256, 2) heads_kernel(
    const float* __restrict__ W_mu, const float* __restrict__ b_mu,
    const float* __restrict__ W_var, const float* __restrict__ b_var,
    const float* __restrict__ hhat,
    float* __restrict__ mu_out, float* __restrict__ var_out)
{
    __shared__ float xs[KT3][BMP];
    __shared__ float ws[KT3][128];  // [ W_mu | W_var ]

    const int n    = blockIdx.x;
    const int b0   = blockIdx.y * BM2;
    const int t    = threadIdx.x;
    const int lane = t & 31;
    const int wid  = t >> 5;
    const int m_base = wid * 8;

    unsigned long long acc[4][4];
#pragma unroll
    for (int p = 0; p < 4; p++)
#pragma unroll
        for (int j = 0; j < 4; j++) acc[p][j] = 0ULL;

    for (int kt = 0; kt < En; kt += KT3) {
        // fill xs: 64 rows x 32 k (coalesced: 128B runs)
#pragma unroll
        for (int i = 0; i < (BM2 * KT3) / 256; i++) {
            int idx = t + i * 256;
            int m  = idx >> 5;
            int kk = idx & 31;
            xs[kk][m] = hhat[((size_t)(b0 + m) * Nn + n) * En + kt + kk];
        }
        // fill ws: 32 k x (64 mu | 64 var)
#pragma unroll
        for (int i = 0; i < (KT3 * 128) / 256; i++) {
            int idx = t + i * 256;
            int kk = idx >> 7;
            int c  = idx & 127;
            float v;
            if (c < 64)
                v = W_mu[((size_t)n * En + kt + kk) * LATn + c];
            else
                v = W_var[((size_t)n * En + kt + kk) * LATn + (c - 64)];
            ws[kk][c] = v;
        }
        __syncthreads();

#pragma unroll
        for (int kk = 0; kk < KT3; kk++) {
            unsigned long long xpair[4];
#pragma unroll
            for (int p = 0; p < 4; p++)
                xpair[p] = *reinterpret_cast<const unsigned long long*>(
                    &xs[kk][m_base + 2 * p]);
#pragma unroll
            for (int j = 0; j < 4; j++) {
                unsigned long long w2 = bcast2(ws[kk][lane + 32 * j]);
#pragma unroll
                for (int p = 0; p < 4; p++)
                    acc[p][j] = ffma2(xpair[p], w2, acc[p][j]);
            }
        }
        __syncthreads();
    }

    // epilogue: j=0,1 -> mu cols, j=2,3 -> var cols
#pragma unroll
    for (int j = 0; j < 4; j++) {
        const int c = lane + 32 * j;
        const bool is_mu = (c < 64);
        const int col = is_mu ? c : (c - 64);
        const float bias = is_mu ? b_mu[n * LATn + col] : b_var[n * LATn + col];
        float* __restrict__ dst = is_mu ? mu_out : var_out;
#pragma unroll
        for (int p = 0; p < 4; p++) {
            float2 hv = unpk(acc[p][j]);
            const int b_r = b0 + m_base + 2 * p;
            const int i0 = ((b_r) * Nn + n) * LATn + col;
            const int i1 = i0 + Nn * LATn;
            dst[i0] = hv.x + bias;
            dst[i1] = hv.y + bias;
        }
    }
}

// ---------------------------------------------------------------------------
// Launch
// ---------------------------------------------------------------------------
extern "C" void kernel_launch(void* const* d_in, const int* in_sizes, int n_in,
                              void* d_out, int out_size) {
    const float* x       = (const float*)d_in[0];
    const float* time_x  = (const float*)d_in[1];
    const float* W_embed = (const float*)d_in[2];
    const float* b_embed = (const float*)d_in[3];
    const float* W_mu    = (const float*)d_in[4];
    const float* b_mu    = (const float*)d_in[5];
    const float* W_var   = (const float*)d_in[6];
    const float* b_var   = (const float*)d_in[7];

    float* out  = (float*)d_out;
    float* h    = out;
    float* hhat = out + HN;
    float* mu   = out + 2 * HN;
    float* var  = out + 2 * HN + LATSZ;

    // 1) transpose x -> g_xp
    dim3 tgrid((Nn + 31) / 32, (Ln + 31) / 32, Bn);
    transpose_kernel<<<tgrid, dim3(32, 8)>>>(x);

    // 2) embed GEMM + sigmoid gating
    embed_kernel<<<dim3(Nn, Bn / BM2), 256>>>(W_embed, b_embed, time_x, h, hhat);

    // 3) mu / var heads
    heads_kernel<<<dim3(Nn, Bn / BM2), 256>>>(W_mu, b_mu, W_var, b_var, hhat, mu, var);
}